// round 2
// baseline (speedup 1.0000x reference)
#include <cuda_runtime.h>
#include <math.h>

#define NTOK 4096
#define DH   1024
#define IH   2048
#define NE   8
#define CAP  1280

// ---- scratch (static device globals; no allocation) ----
__device__ float g_act[(size_t)NE * CAP * IH];    // post-GLU activations  [E,cap,I]
__device__ float g_eout[(size_t)NE * CAP * DH];   // expert outputs        [E,cap,D]
__device__ int   g_tok[NE * CAP];                 // token id per expert slot
__device__ int   g_cnt[NE];                       // min(total per expert, cap)
__device__ int   g_slot_e[NTOK * 2];              // expert id per (token,k) slot
__device__ int   g_slot_p[NTOK * 2];              // position within expert (may be >= CAP if dropped)
__device__ float g_slot_g[NTOK * 2];              // gate per slot

__device__ __forceinline__ float gelu_exact(float v) {
    return 0.5f * v * (1.f + erff(v * 0.70710678118654752f));
}

// ---------------- router: logits, top-2, softmax ----------------
__global__ __launch_bounds__(256) void router_kernel(const float* __restrict__ x,
                                                     const float* __restrict__ Wg) {
    int warp = (blockIdx.x * 256 + threadIdx.x) >> 5;
    int lane = threadIdx.x & 31;
    if (warp >= NTOK) return;
    const float* xr = x + (size_t)warp * DH;
    float acc[NE];
#pragma unroll
    for (int e = 0; e < NE; e++) acc[e] = 0.f;
    for (int d = lane; d < DH; d += 32) {
        float xv = xr[d];
#pragma unroll
        for (int e = 0; e < NE; e++) acc[e] += xv * Wg[e * DH + d];
    }
#pragma unroll
    for (int off = 16; off; off >>= 1) {
#pragma unroll
        for (int e = 0; e < NE; e++) acc[e] += __shfl_xor_sync(0xffffffffu, acc[e], off);
    }
    if (lane == 0) {
        int i0 = 0; float v0 = acc[0];
#pragma unroll
        for (int e = 1; e < NE; e++) if (acc[e] > v0) { v0 = acc[e]; i0 = e; }
        int i1 = -1; float v1 = -1e30f;
#pragma unroll
        for (int e = 0; e < NE; e++) if (e != i0 && acc[e] > v1) { v1 = acc[e]; i1 = e; }
        float g0 = 1.f / (1.f + expf(v1 - v0));   // softmax over [v0,v1], v0 >= v1
        g_slot_e[warp * 2 + 0] = i0;
        g_slot_e[warp * 2 + 1] = i1;
        g_slot_g[warp * 2 + 0] = g0;
        g_slot_g[warp * 2 + 1] = 1.f - g0;
    }
}

// ---------------- greedy capacity assignment (exact slot-order prefix counts) ----------------
__global__ __launch_bounds__(256) void assign_kernel() {
    __shared__ int sh[256][NE];
    int t = threadIdx.x;
    int base = t * 32;                     // 256 threads * 32 slots = 8192 slots
    int cnt[NE];
#pragma unroll
    for (int e = 0; e < NE; e++) cnt[e] = 0;
    int ebuf[32];
#pragma unroll
    for (int s = 0; s < 32; s++) {
        int e = g_slot_e[base + s];
        ebuf[s] = e;
        cnt[e]++;
    }
#pragma unroll
    for (int e = 0; e < NE; e++) sh[t][e] = cnt[e];
    __syncthreads();
    // inclusive Hillis-Steele scan over threads (vector of NE counters)
    for (int off = 1; off < 256; off <<= 1) {
        int v[NE];
        if (t >= off) {
#pragma unroll
            for (int e = 0; e < NE; e++) v[e] = sh[t - off][e];
        }
        __syncthreads();
        if (t >= off) {
#pragma unroll
            for (int e = 0; e < NE; e++) sh[t][e] += v[e];
        }
        __syncthreads();
    }
    int excl[NE], run[NE];
#pragma unroll
    for (int e = 0; e < NE; e++) { excl[e] = sh[t][e] - cnt[e]; run[e] = 0; }
    if (t == 255) {
#pragma unroll
        for (int e = 0; e < NE; e++) {
            int tot = sh[255][e];
            g_cnt[e] = tot < CAP ? tot : CAP;
        }
    }
#pragma unroll
    for (int s = 0; s < 32; s++) {
        int e = ebuf[s];
        int p = excl[e] + run[e];
        run[e]++;
        g_slot_p[base + s] = p;
        if (p < CAP) g_tok[e * CAP + p] = (base + s) >> 1;   // token id
    }
}

// ---------------- GEMM1 + GLU fused: act[e,m,i] = gelu(x@W1[:, i]) * (x@W1[:, i+IH]) ----------------
// Block tile: 128 rows (tokens) x 64 act-cols; accumulates paired inp/gate tiles (128 acc cols).
__global__ __launch_bounds__(256) void gemm1_glu_kernel(const float* __restrict__ x,
                                                        const float* __restrict__ W1) {
    int e = blockIdx.z;
    int cnt = g_cnt[e];
    int m0 = blockIdx.y * 128;
    if (m0 >= cnt) return;
    int n0 = blockIdx.x * 64;              // act column base
    __shared__ float As[16][128];          // [k][m]
    __shared__ float Bs[16][128];          // cols 0..63: inp (W1 col n0+j); 64..127: gate (W1 col n0+IH+j)
    int tid = threadIdx.x;

    // A loader: row ra, cols [ca, ca+8)
    int ra = tid & 127;
    int ca = (tid >> 7) * 8;
    int gm = m0 + ra;
    int tokrow = (gm < cnt) ? g_tok[e * CAP + gm] : 0;
    const float* arow = x + (size_t)tokrow * DH;

    // B loader: row rb, cols [cb, cb+8) of the 128-wide combined tile
    int rb = tid >> 4;
    int cb = (tid & 15) * 8;
    const float* Bbase = W1 + (size_t)e * DH * (2 * IH);
    int bcol = (cb < 64) ? (n0 + cb) : (n0 + IH + (cb - 64));

    float acc[8][8];
#pragma unroll
    for (int i = 0; i < 8; i++)
#pragma unroll
        for (int j = 0; j < 8; j++) acc[i][j] = 0.f;

    int c = (tid & 15) * 4;   // col base within 64 (4+4 split)
    int r = (tid >> 4) * 4;   // row base within 64 (4+4 split)

    for (int k0 = 0; k0 < DH; k0 += 16) {
        float4 a0 = *(const float4*)(arow + k0 + ca);
        float4 a1 = *(const float4*)(arow + k0 + ca + 4);
        As[ca + 0][ra] = a0.x; As[ca + 1][ra] = a0.y; As[ca + 2][ra] = a0.z; As[ca + 3][ra] = a0.w;
        As[ca + 4][ra] = a1.x; As[ca + 5][ra] = a1.y; As[ca + 6][ra] = a1.z; As[ca + 7][ra] = a1.w;
        const float* bp = Bbase + (size_t)(k0 + rb) * (2 * IH) + bcol;
        *(float4*)&Bs[rb][cb]     = *(const float4*)bp;
        *(float4*)&Bs[rb][cb + 4] = *(const float4*)(bp + 4);
        __syncthreads();
#pragma unroll
        for (int kk = 0; kk < 16; kk++) {
            float4 av0 = *(const float4*)&As[kk][r];
            float4 av1 = *(const float4*)&As[kk][64 + r];
            float4 bv0 = *(const float4*)&Bs[kk][c];        // inp cols c..c+3
            float4 bv1 = *(const float4*)&Bs[kk][64 + c];   // gate cols c..c+3
            float a[8] = {av0.x, av0.y, av0.z, av0.w, av1.x, av1.y, av1.z, av1.w};
            float b[8] = {bv0.x, bv0.y, bv0.z, bv0.w, bv1.x, bv1.y, bv1.z, bv1.w};
#pragma unroll
            for (int i = 0; i < 8; i++)
#pragma unroll
                for (int j = 0; j < 8; j++) acc[i][j] += a[i] * b[j];
        }
        __syncthreads();
    }

    // epilogue: act = gelu(inp) * gate ; acc[i][j<4]=inp, acc[i][j+4]=gate (same act col)
    float* actb = g_act + (size_t)e * CAP * IH;
#pragma unroll
    for (int i = 0; i < 8; i++) {
        int m = m0 + ((i < 4) ? (r + i) : (64 + r + i - 4));
        float4 o;
        o.x = gelu_exact(acc[i][0]) * acc[i][4];
        o.y = gelu_exact(acc[i][1]) * acc[i][5];
        o.z = gelu_exact(acc[i][2]) * acc[i][6];
        o.w = gelu_exact(acc[i][3]) * acc[i][7];
        *(float4*)(actb + (size_t)m * IH + n0 + c) = o;
    }
}

// ---------------- GEMM2: exp_out = act @ W2[e]  ([cnt,2048] x [2048,1024]) ----------------
__global__ __launch_bounds__(256) void gemm2_kernel(const float* __restrict__ W2) {
    int e = blockIdx.z;
    int cnt = g_cnt[e];
    int m0 = blockIdx.y * 128;
    if (m0 >= cnt) return;
    int n0 = blockIdx.x * 128;
    __shared__ float As[16][128];
    __shared__ float Bs[16][128];
    int tid = threadIdx.x;

    int ra = tid & 127;
    int ca = (tid >> 7) * 8;
    const float* arow = g_act + (size_t)e * CAP * IH + (size_t)(m0 + ra) * IH;

    int rb = tid >> 4;
    int cb = (tid & 15) * 8;
    const float* Bbase = W2 + (size_t)e * IH * DH;

    float acc[8][8];
#pragma unroll
    for (int i = 0; i < 8; i++)
#pragma unroll
        for (int j = 0; j < 8; j++) acc[i][j] = 0.f;

    int c = (tid & 15) * 4;
    int r = (tid >> 4) * 4;

    for (int k0 = 0; k0 < IH; k0 += 16) {
        float4 a0 = *(const float4*)(arow + k0 + ca);
        float4 a1 = *(const float4*)(arow + k0 + ca + 4);
        As[ca + 0][ra] = a0.x; As[ca + 1][ra] = a0.y; As[ca + 2][ra] = a0.z; As[ca + 3][ra] = a0.w;
        As[ca + 4][ra] = a1.x; As[ca + 5][ra] = a1.y; As[ca + 6][ra] = a1.z; As[ca + 7][ra] = a1.w;
        const float* bp = Bbase + (size_t)(k0 + rb) * DH + n0 + cb;
        *(float4*)&Bs[rb][cb]     = *(const float4*)bp;
        *(float4*)&Bs[rb][cb + 4] = *(const float4*)(bp + 4);
        __syncthreads();
#pragma unroll
        for (int kk = 0; kk < 16; kk++) {
            float4 av0 = *(const float4*)&As[kk][r];
            float4 av1 = *(const float4*)&As[kk][64 + r];
            float4 bv0 = *(const float4*)&Bs[kk][c];
            float4 bv1 = *(const float4*)&Bs[kk][64 + c];
            float a[8] = {av0.x, av0.y, av0.z, av0.w, av1.x, av1.y, av1.z, av1.w};
            float b[8] = {bv0.x, bv0.y, bv0.z, bv0.w, bv1.x, bv1.y, bv1.z, bv1.w};
#pragma unroll
            for (int i = 0; i < 8; i++)
#pragma unroll
                for (int j = 0; j < 8; j++) acc[i][j] += a[i] * b[j];
        }
        __syncthreads();
    }

    float* cbase = g_eout + (size_t)e * CAP * DH;
#pragma unroll
    for (int i = 0; i < 8; i++) {
        int m = m0 + ((i < 4) ? (r + i) : (64 + r + i - 4));
        float4 o0 = {acc[i][0], acc[i][1], acc[i][2], acc[i][3]};
        float4 o1 = {acc[i][4], acc[i][5], acc[i][6], acc[i][7]};
        *(float4*)(cbase + (size_t)m * DH + n0 + c)      = o0;
        *(float4*)(cbase + (size_t)m * DH + n0 + 64 + c) = o1;
    }
}

// ---------------- combine: out[t] = sum_k keep * gate * exp_out[e, pos] ----------------
__global__ __launch_bounds__(256) void combine_kernel(float* __restrict__ out) {
    int t = blockIdx.x;
    int e0 = g_slot_e[2 * t + 0], p0 = g_slot_p[2 * t + 0];
    int e1 = g_slot_e[2 * t + 1], p1 = g_slot_p[2 * t + 1];
    float g0 = g_slot_g[2 * t + 0], g1 = g_slot_g[2 * t + 1];
    bool k0 = p0 < CAP, k1 = p1 < CAP;
    const float* r0 = g_eout + ((size_t)e0 * CAP + (size_t)(k0 ? p0 : 0)) * DH;
    const float* r1 = g_eout + ((size_t)e1 * CAP + (size_t)(k1 ? p1 : 0)) * DH;
    for (int d = threadIdx.x; d < DH; d += 256) {
        float v = 0.f;
        if (k0) v += g0 * r0[d];
        if (k1) v += g1 * r1[d];
        out[(size_t)t * DH + d] = v;
    }
}

extern "C" void kernel_launch(void* const* d_in, const int* in_sizes, int n_in,
                              void* d_out, int out_size) {
    const float* x  = (const float*)d_in[0];   // [2,2048,1024]
    const float* Wg = (const float*)d_in[1];   // [8,1024]
    const float* W1 = (const float*)d_in[2];   // [8,1024,4096]
    const float* W2 = (const float*)d_in[3];   // [8,2048,1024]
    float* out = (float*)d_out;                // [2,2048,1024]

    router_kernel<<<NTOK / 8, 256>>>(x, Wg);
    assign_kernel<<<1, 256>>>();
    gemm1_glu_kernel<<<dim3(IH / 64, CAP / 128, NE), 256>>>(x, W1);
    gemm2_kernel<<<dim3(DH / 128, CAP / 128, NE), 256>>>(W2);
    combine_kernel<<<NTOK, 256>>>(out);
}

// round 10
// speedup vs baseline: 1.5631x; 1.5631x over previous
#include <cuda_runtime.h>
#include <math.h>
#include <stdint.h>

#define NTOK 4096
#define DH   1024
#define IH   2048
#define NE   8
#define CAP  1280

// ---- scratch (static device globals; no allocation) ----
__device__ float g_act[(size_t)NE * CAP * IH];        // post-GLU activations  [E,cap,I]
__device__ float g_eout[(size_t)NE * CAP * DH];       // expert outputs        [E,cap,D]
__device__ float g_wT1[(size_t)NE * (2 * IH) * DH];   // W1 transposed: [e][n<4096][k<1024]
__device__ float g_wT2[(size_t)NE * DH * IH];         // W2 transposed: [e][n<1024][k<2048]
__device__ int   g_tok[NE * CAP];
__device__ int   g_cnt[NE];
__device__ int   g_slot_e[NTOK * 2];
__device__ int   g_slot_p[NTOK * 2];
__device__ float g_slot_g[NTOK * 2];

__device__ __forceinline__ float gelu_exact(float v) {
    return 0.5f * v * (1.f + erff(v * 0.70710678118654752f));
}
__device__ __forceinline__ float to_tf32(float v) {
    uint32_t t;
    asm("cvt.rna.tf32.f32 %0, %1;" : "=r"(t) : "f"(v));
    return __uint_as_float(t);
}
#define MMA_TF32(c, a, b) \
    asm volatile("mma.sync.aligned.m16n8k8.row.col.f32.tf32.tf32.f32 " \
        "{%0,%1,%2,%3}, {%4,%5,%6,%7}, {%8,%9}, {%0,%1,%2,%3};" \
        : "+f"((c)[0]), "+f"((c)[1]), "+f"((c)[2]), "+f"((c)[3]) \
        : "r"((a)[0]), "r"((a)[1]), "r"((a)[2]), "r"((a)[3]), \
          "r"((b)[0]), "r"((b)[1]))

// ================= weight transposes =================
__global__ __launch_bounds__(256) void transpose_w1_kernel(const float* __restrict__ in) {
    const int R = DH, C = 2 * IH;
    __shared__ float t[32][33];
    const float* ine = in + (size_t)blockIdx.z * R * C;
    float* oute = g_wT1 + (size_t)blockIdx.z * R * C;
    int c0 = blockIdx.x * 32, r0 = blockIdx.y * 32;
    int tx = threadIdx.x, ty = threadIdx.y;   // (32, 8)
#pragma unroll
    for (int i = 0; i < 32; i += 8)
        t[ty + i][tx] = ine[(size_t)(r0 + ty + i) * C + c0 + tx];
    __syncthreads();
#pragma unroll
    for (int i = 0; i < 32; i += 8)
        oute[(size_t)(c0 + ty + i) * R + r0 + tx] = t[tx][ty + i];
}
__global__ __launch_bounds__(256) void transpose_w2_kernel(const float* __restrict__ in) {
    const int R = IH, C = DH;
    __shared__ float t[32][33];
    const float* ine = in + (size_t)blockIdx.z * R * C;
    float* oute = g_wT2 + (size_t)blockIdx.z * R * C;
    int c0 = blockIdx.x * 32, r0 = blockIdx.y * 32;
    int tx = threadIdx.x, ty = threadIdx.y;
#pragma unroll
    for (int i = 0; i < 32; i += 8)
        t[ty + i][tx] = ine[(size_t)(r0 + ty + i) * C + c0 + tx];
    __syncthreads();
#pragma unroll
    for (int i = 0; i < 32; i += 8)
        oute[(size_t)(c0 + ty + i) * R + r0 + tx] = t[tx][ty + i];
}

// ================= router =================
__global__ __launch_bounds__(256) void router_kernel(const float* __restrict__ x,
                                                     const float* __restrict__ Wg) {
    int warp = (blockIdx.x * 256 + threadIdx.x) >> 5;
    int lane = threadIdx.x & 31;
    if (warp >= NTOK) return;
    const float* xr = x + (size_t)warp * DH;
    float acc[NE];
#pragma unroll
    for (int e = 0; e < NE; e++) acc[e] = 0.f;
    for (int d = lane; d < DH; d += 32) {
        float xv = xr[d];
#pragma unroll
        for (int e = 0; e < NE; e++) acc[e] += xv * Wg[e * DH + d];
    }
#pragma unroll
    for (int off = 16; off; off >>= 1) {
#pragma unroll
        for (int e = 0; e < NE; e++) acc[e] += __shfl_xor_sync(0xffffffffu, acc[e], off);
    }
    if (lane == 0) {
        int i0 = 0; float v0 = acc[0];
#pragma unroll
        for (int e = 1; e < NE; e++) if (acc[e] > v0) { v0 = acc[e]; i0 = e; }
        int i1 = -1; float v1 = -1e30f;
#pragma unroll
        for (int e = 0; e < NE; e++) if (e != i0 && acc[e] > v1) { v1 = acc[e]; i1 = e; }
        float g0 = 1.f / (1.f + expf(v1 - v0));
        g_slot_e[warp * 2 + 0] = i0;
        g_slot_e[warp * 2 + 1] = i1;
        g_slot_g[warp * 2 + 0] = g0;
        g_slot_g[warp * 2 + 1] = 1.f - g0;
    }
}

// ================= greedy capacity assignment =================
__global__ __launch_bounds__(256) void assign_kernel() {
    __shared__ int sh[256][NE];
    int t = threadIdx.x;
    int base = t * 32;
    int cnt[NE];
#pragma unroll
    for (int e = 0; e < NE; e++) cnt[e] = 0;
    int ebuf[32];
#pragma unroll
    for (int s = 0; s < 32; s++) {
        int e = g_slot_e[base + s];
        ebuf[s] = e;
        cnt[e]++;
    }
#pragma unroll
    for (int e = 0; e < NE; e++) sh[t][e] = cnt[e];
    __syncthreads();
    for (int off = 1; off < 256; off <<= 1) {
        int v[NE];
        if (t >= off) {
#pragma unroll
            for (int e = 0; e < NE; e++) v[e] = sh[t - off][e];
        }
        __syncthreads();
        if (t >= off) {
#pragma unroll
            for (int e = 0; e < NE; e++) sh[t][e] += v[e];
        }
        __syncthreads();
    }
    int excl[NE], run[NE];
#pragma unroll
    for (int e = 0; e < NE; e++) { excl[e] = sh[t][e] - cnt[e]; run[e] = 0; }
    if (t == 255) {
#pragma unroll
        for (int e = 0; e < NE; e++) {
            int tot = sh[255][e];
            g_cnt[e] = tot < CAP ? tot : CAP;
        }
    }
#pragma unroll
    for (int s = 0; s < 32; s++) {
        int e = ebuf[s];
        int p = excl[e] + run[e];
        run[e]++;
        g_slot_p[base + s] = p;
        if (p < CAP) g_tok[e * CAP + p] = (base + s) >> 1;
    }
}

// ================= GEMM1 + fused GLU (mma.sync tf32) =================
// Block: 128 rows x 64 act cols (= 128 B-cols: per 32-col band, 16 inp + 16 gate).
// Warps: 2 (M, 64 rows) x 4 (N, 32 B-cols). c[mt][nt] inp pairs with c[mt][nt+2] gate.
__global__ __launch_bounds__(256) void gemm1_mma(const float* __restrict__ x) {
    __shared__ float As[2][16][136];
    __shared__ float Bs[2][128][20];
    int e = blockIdx.z;
    int cnt = g_cnt[e];
    int m0 = blockIdx.y * 128;
    if (m0 >= cnt) return;
    int n0 = blockIdx.x * 64;   // act col base
    int tid = threadIdx.x;

    // loaders: lrow = tid&127 (row of A tile / row of B tile), lseg = 0/8 k-offset
    int lrow = tid & 127;
    int lseg = (tid >> 7) * 8;
    int gm = m0 + lrow;
    int tok = (gm < cnt) ? g_tok[e * CAP + gm] : 0;
    const float* arow = x + (size_t)tok * DH;
    int wcb = lrow >> 5, off = lrow & 31;
    int gcol = (off < 16) ? (n0 + wcb * 16 + off) : (IH + n0 + wcb * 16 + (off - 16));
    const float* brow = g_wT1 + (size_t)e * (2 * IH) * DH + (size_t)gcol * DH;

    int w = tid >> 5, lane = tid & 31;
    int wr = w & 1, wc = w >> 1;
    int grp = lane >> 2, tig = lane & 3;

    float c[4][4][4];
#pragma unroll
    for (int i = 0; i < 4; i++)
#pragma unroll
        for (int j = 0; j < 4; j++)
#pragma unroll
            for (int q = 0; q < 4; q++) c[i][j][q] = 0.f;

    // prologue: tile 0
    {
        float4 a0 = *(const float4*)(arow + lseg);
        float4 a1 = *(const float4*)(arow + lseg + 4);
        float4 b0 = *(const float4*)(brow + lseg);
        float4 b1 = *(const float4*)(brow + lseg + 4);
        As[0][lseg + 0][lrow] = to_tf32(a0.x); As[0][lseg + 1][lrow] = to_tf32(a0.y);
        As[0][lseg + 2][lrow] = to_tf32(a0.z); As[0][lseg + 3][lrow] = to_tf32(a0.w);
        As[0][lseg + 4][lrow] = to_tf32(a1.x); As[0][lseg + 5][lrow] = to_tf32(a1.y);
        As[0][lseg + 6][lrow] = to_tf32(a1.z); As[0][lseg + 7][lrow] = to_tf32(a1.w);
        float4 tb0 = {to_tf32(b0.x), to_tf32(b0.y), to_tf32(b0.z), to_tf32(b0.w)};
        float4 tb1 = {to_tf32(b1.x), to_tf32(b1.y), to_tf32(b1.z), to_tf32(b1.w)};
        *(float4*)&Bs[0][lrow][lseg] = tb0;
        *(float4*)&Bs[0][lrow][lseg + 4] = tb1;
    }
    __syncthreads();

    const int KT = DH / 16;   // 64
    float ra[8], rb[8];
    for (int kt = 0; kt < KT; kt++) {
        int buf = kt & 1;
        if (kt + 1 < KT) {
            int k0 = (kt + 1) * 16 + lseg;
            float4 a0 = *(const float4*)(arow + k0);
            float4 a1 = *(const float4*)(arow + k0 + 4);
            float4 b0 = *(const float4*)(brow + k0);
            float4 b1 = *(const float4*)(brow + k0 + 4);
            ra[0] = a0.x; ra[1] = a0.y; ra[2] = a0.z; ra[3] = a0.w;
            ra[4] = a1.x; ra[5] = a1.y; ra[6] = a1.z; ra[7] = a1.w;
            rb[0] = b0.x; rb[1] = b0.y; rb[2] = b0.z; rb[3] = b0.w;
            rb[4] = b1.x; rb[5] = b1.y; rb[6] = b1.z; rb[7] = b1.w;
        }
#pragma unroll
        for (int ks = 0; ks < 2; ks++) {
            int kb = ks * 8;
            uint32_t af[4][4], bf[4][2];
#pragma unroll
            for (int mt = 0; mt < 4; mt++) {
                int mr = wr * 64 + mt * 16 + grp;
                af[mt][0] = __float_as_uint(As[buf][kb + tig][mr]);
                af[mt][1] = __float_as_uint(As[buf][kb + tig][mr + 8]);
                af[mt][2] = __float_as_uint(As[buf][kb + tig + 4][mr]);
                af[mt][3] = __float_as_uint(As[buf][kb + tig + 4][mr + 8]);
            }
#pragma unroll
            for (int nt = 0; nt < 4; nt++) {
                int nr = wc * 32 + nt * 8 + grp;
                bf[nt][0] = __float_as_uint(Bs[buf][nr][kb + tig]);
                bf[nt][1] = __float_as_uint(Bs[buf][nr][kb + tig + 4]);
            }
#pragma unroll
            for (int mt = 0; mt < 4; mt++)
#pragma unroll
                for (int nt = 0; nt < 4; nt++)
                    MMA_TF32(c[mt][nt], af[mt], bf[nt]);
        }
        if (kt + 1 < KT) {
            int nb = buf ^ 1;
            As[nb][lseg + 0][lrow] = to_tf32(ra[0]); As[nb][lseg + 1][lrow] = to_tf32(ra[1]);
            As[nb][lseg + 2][lrow] = to_tf32(ra[2]); As[nb][lseg + 3][lrow] = to_tf32(ra[3]);
            As[nb][lseg + 4][lrow] = to_tf32(ra[4]); As[nb][lseg + 5][lrow] = to_tf32(ra[5]);
            As[nb][lseg + 6][lrow] = to_tf32(ra[6]); As[nb][lseg + 7][lrow] = to_tf32(ra[7]);
            float4 tb0 = {to_tf32(rb[0]), to_tf32(rb[1]), to_tf32(rb[2]), to_tf32(rb[3])};
            float4 tb1 = {to_tf32(rb[4]), to_tf32(rb[5]), to_tf32(rb[6]), to_tf32(rb[7])};
            *(float4*)&Bs[nb][lrow][lseg] = tb0;
            *(float4*)&Bs[nb][lrow][lseg + 4] = tb1;
        }
        __syncthreads();
    }

    // epilogue: act = gelu(inp) * gate ; inp = c[mt][nt], gate = c[mt][nt+2]
    float* actb = g_act + (size_t)e * CAP * IH;
#pragma unroll
    for (int mt = 0; mt < 4; mt++) {
        int mbase = m0 + wr * 64 + mt * 16;
#pragma unroll
        for (int nt = 0; nt < 2; nt++) {
            int col = n0 + wc * 16 + nt * 8 + 2 * tig;
            float2 o0 = {gelu_exact(c[mt][nt][0]) * c[mt][nt + 2][0],
                         gelu_exact(c[mt][nt][1]) * c[mt][nt + 2][1]};
            float2 o1 = {gelu_exact(c[mt][nt][2]) * c[mt][nt + 2][2],
                         gelu_exact(c[mt][nt][3]) * c[mt][nt + 2][3]};
            *(float2*)(actb + (size_t)(mbase + grp) * IH + col) = o0;
            *(float2*)(actb + (size_t)(mbase + grp + 8) * IH + col) = o1;
        }
    }
}

// ================= GEMM2 (mma.sync tf32): eout = act @ W2 =================
__global__ __launch_bounds__(256) void gemm2_mma() {
    __shared__ float As[2][16][136];
    __shared__ float Bs[2][128][20];
    int e = blockIdx.z;
    int cnt = g_cnt[e];
    int m0 = blockIdx.y * 128;
    if (m0 >= cnt) return;
    int n0 = blockIdx.x * 128;
    int tid = threadIdx.x;

    int lrow = tid & 127;
    int lseg = (tid >> 7) * 8;
    const float* arow = g_act + ((size_t)e * CAP + m0 + lrow) * IH;
    const float* brow = g_wT2 + (size_t)e * DH * IH + (size_t)(n0 + lrow) * IH;

    int w = tid >> 5, lane = tid & 31;
    int wr = w & 1, wc = w >> 1;
    int grp = lane >> 2, tig = lane & 3;

    float c[4][4][4];
#pragma unroll
    for (int i = 0; i < 4; i++)
#pragma unroll
        for (int j = 0; j < 4; j++)
#pragma unroll
            for (int q = 0; q < 4; q++) c[i][j][q] = 0.f;

    {
        float4 a0 = *(const float4*)(arow + lseg);
        float4 a1 = *(const float4*)(arow + lseg + 4);
        float4 b0 = *(const float4*)(brow + lseg);
        float4 b1 = *(const float4*)(brow + lseg + 4);
        As[0][lseg + 0][lrow] = to_tf32(a0.x); As[0][lseg + 1][lrow] = to_tf32(a0.y);
        As[0][lseg + 2][lrow] = to_tf32(a0.z); As[0][lseg + 3][lrow] = to_tf32(a0.w);
        As[0][lseg + 4][lrow] = to_tf32(a1.x); As[0][lseg + 5][lrow] = to_tf32(a1.y);
        As[0][lseg + 6][lrow] = to_tf32(a1.z); As[0][lseg + 7][lrow] = to_tf32(a1.w);
        float4 tb0 = {to_tf32(b0.x), to_tf32(b0.y), to_tf32(b0.z), to_tf32(b0.w)};
        float4 tb1 = {to_tf32(b1.x), to_tf32(b1.y), to_tf32(b1.z), to_tf32(b1.w)};
        *(float4*)&Bs[0][lrow][lseg] = tb0;
        *(float4*)&Bs[0][lrow][lseg + 4] = tb1;
    }
    __syncthreads();

    const int KT = IH / 16;   // 128
    float ra[8], rb[8];
    for (int kt = 0; kt < KT; kt++) {
        int buf = kt & 1;
        if (kt + 1 < KT) {
            int k0 = (kt + 1) * 16 + lseg;
            float4 a0 = *(const float4*)(arow + k0);
            float4 a1 = *(const float4*)(arow + k0 + 4);
            float4 b0 = *(const float4*)(brow + k0);
            float4 b1 = *(const float4*)(brow + k0 + 4);
            ra[0] = a0.x; ra[1] = a0.y; ra[2] = a0.z; ra[3] = a0.w;
            ra[4] = a1.x; ra[5] = a1.y; ra[6] = a1.z; ra[7] = a1.w;
            rb[0] = b0.x; rb[1] = b0.y; rb[2] = b0.z; rb[3] = b0.w;
            rb[4] = b1.x; rb[5] = b1.y; rb[6] = b1.z; rb[7] = b1.w;
        }
#pragma unroll
        for (int ks = 0; ks < 2; ks++) {
            int kb = ks * 8;
            uint32_t af[4][4], bf[4][2];
#pragma unroll
            for (int mt = 0; mt < 4; mt++) {
                int mr = wr * 64 + mt * 16 + grp;
                af[mt][0] = __float_as_uint(As[buf][kb + tig][mr]);
                af[mt][1] = __float_as_uint(As[buf][kb + tig][mr + 8]);
                af[mt][2] = __float_as_uint(As[buf][kb + tig + 4][mr]);
                af[mt][3] = __float_as_uint(As[buf][kb + tig + 4][mr + 8]);
            }
#pragma unroll
            for (int nt = 0; nt < 4; nt++) {
                int nr = wc * 32 + nt * 8 + grp;
                bf[nt][0] = __float_as_uint(Bs[buf][nr][kb + tig]);
                bf[nt][1] = __float_as_uint(Bs[buf][nr][kb + tig + 4]);
            }
#pragma unroll
            for (int mt = 0; mt < 4; mt++)
#pragma unroll
                for (int nt = 0; nt < 4; nt++)
                    MMA_TF32(c[mt][nt], af[mt], bf[nt]);
        }
        if (kt + 1 < KT) {
            int nb = buf ^ 1;
            As[nb][lseg + 0][lrow] = to_tf32(ra[0]); As[nb][lseg + 1][lrow] = to_tf32(ra[1]);
            As[nb][lseg + 2][lrow] = to_tf32(ra[2]); As[nb][lseg + 3][lrow] = to_tf32(ra[3]);
            As[nb][lseg + 4][lrow] = to_tf32(ra[4]); As[nb][lseg + 5][lrow] = to_tf32(ra[5]);
            As[nb][lseg + 6][lrow] = to_tf32(ra[6]); As[nb][lseg + 7][lrow] = to_tf32(ra[7]);
            float4 tb0 = {to_tf32(rb[0]), to_tf32(rb[1]), to_tf32(rb[2]), to_tf32(rb[3])};
            float4 tb1 = {to_tf32(rb[4]), to_tf32(rb[5]), to_tf32(rb[6]), to_tf32(rb[7])};
            *(float4*)&Bs[nb][lrow][lseg] = tb0;
            *(float4*)&Bs[nb][lrow][lseg + 4] = tb1;
        }
        __syncthreads();
    }

    float* outb = g_eout + (size_t)e * CAP * DH;
#pragma unroll
    for (int mt = 0; mt < 4; mt++) {
        int mbase = m0 + wr * 64 + mt * 16;
#pragma unroll
        for (int nt = 0; nt < 4; nt++) {
            int col = n0 + wc * 32 + nt * 8 + 2 * tig;
            float2 o0 = {c[mt][nt][0], c[mt][nt][1]};
            float2 o1 = {c[mt][nt][2], c[mt][nt][3]};
            *(float2*)(outb + (size_t)(mbase + grp) * DH + col) = o0;
            *(float2*)(outb + (size_t)(mbase + grp + 8) * DH + col) = o1;
        }
    }
}

// ================= combine =================
__global__ __launch_bounds__(256) void combine_kernel(float* __restrict__ out) {
    int t = blockIdx.x;
    int e0 = g_slot_e[2 * t + 0], p0 = g_slot_p[2 * t + 0];
    int e1 = g_slot_e[2 * t + 1], p1 = g_slot_p[2 * t + 1];
    float g0 = g_slot_g[2 * t + 0], g1 = g_slot_g[2 * t + 1];
    bool k0 = p0 < CAP, k1 = p1 < CAP;
    const float* r0 = g_eout + ((size_t)e0 * CAP + (size_t)(k0 ? p0 : 0)) * DH;
    const float* r1 = g_eout + ((size_t)e1 * CAP + (size_t)(k1 ? p1 : 0)) * DH;
    for (int d = threadIdx.x; d < DH; d += 256) {
        float v = 0.f;
        if (k0) v += g0 * r0[d];
        if (k1) v += g1 * r1[d];
        out[(size_t)t * DH + d] = v;
    }
}

extern "C" void kernel_launch(void* const* d_in, const int* in_sizes, int n_in,
                              void* d_out, int out_size) {
    const float* x  = (const float*)d_in[0];   // [2,2048,1024]
    const float* Wg = (const float*)d_in[1];   // [8,1024]
    const float* W1 = (const float*)d_in[2];   // [8,1024,4096]
    const float* W2 = (const float*)d_in[3];   // [8,2048,1024]
    float* out = (float*)d_out;

    transpose_w1_kernel<<<dim3((2 * IH) / 32, DH / 32, NE), dim3(32, 8)>>>(W1);
    transpose_w2_kernel<<<dim3(DH / 32, IH / 32, NE), dim3(32, 8)>>>(W2);
    router_kernel<<<NTOK / 8, 256>>>(x, Wg);
    assign_kernel<<<1, 256>>>();
    gemm1_mma<<<dim3(IH / 64, CAP / 128, NE), 256>>>(x);
    gemm2_mma<<<dim3(DH / 128, CAP / 128, NE), 256>>>();
    combine_kernel<<<NTOK, 256>>>(out);
}